// round 10
// baseline (speedup 1.0000x reference)
#include <cuda_runtime.h>
#include <math.h>

#define BN    737280      // total elements (8 * 92160)
#define NPIX  92160       // elements per (b,t) slice
#define NTRK  512
#define NSEG  4096        // 8 * 512
#define NCH   66
#define WCH   68          // padded accumulator row (16B-aligned stride)
#define REPL  4           // accumulator replicas (contention spreading)
#define THR   2.0f
#define DKS   0.05f

// ---------------- scratch (device globals; no allocation) ----------------
// single struct so one memset clears everything that needs zeroing
struct Scratch {
    int    cnt[REPL * NSEG];
    float4 p1[REPL * NSEG];              // {z1, wx, wy, wz}
    float  wsum[REPL * NSEG * WCH];      // [0..65]=w*ch, [66]=z2
};
__device__ __align__(16) Scratch        g_s;
__device__ unsigned long long           g_repkey[REPL * NSEG];  // (~fok(k0))<<32 | idx
__device__ __align__(16) float          g_srow[NSEG * WCH];     // finalized segment row
__device__ int                          g_rep[NSEG];
__device__ unsigned char                g_flags[BN];

// ordered-uint mapping for floats (bijective, order-preserving)
__device__ __forceinline__ unsigned fok(float f) {
    unsigned b = __float_as_uint(f);
    return (b & 0x80000000u) ? ~b : (b | 0x80000000u);
}
__device__ __forceinline__ float kof(unsigned u) {
    unsigned b = (u & 0x80000000u) ? (u & 0x7FFFFFFFu) : ~u;
    return __uint_as_float(b);
}
__device__ __forceinline__ int seg_of(int i, int g) {
    return (i / NPIX) * NTRK + g;
}
__device__ __forceinline__ void red_add_v4(float* p, float a, float b, float c, float d) {
    asm volatile("red.global.add.v4.f32 [%0], {%1, %2, %3, %4};"
                 :: "l"(p), "f"(a), "f"(b), "f"(c), "f"(d) : "memory");
}

// load all 66 channels for element i into buf
// order: center(0-2) offset(3-5) opacity(6) scale(7-9) rotation(10-13)
//        feat_dc(14-16) keep(17) inst(18-49) motion(50-65)
__device__ __forceinline__ void load_row(
    int i, float* buf,
    const float* __restrict__ cen, const float* __restrict__ off,
    const float* __restrict__ opa, const float* __restrict__ sca,
    const float* __restrict__ rot, const float* __restrict__ fdc,
    const float* __restrict__ kp,  const float* __restrict__ ins,
    const float* __restrict__ mot) {
    #pragma unroll
    for (int c = 0; c < 3; c++) buf[c]      = cen[3 * i + c];
    #pragma unroll
    for (int c = 0; c < 3; c++) buf[3 + c]  = off[3 * i + c];
    buf[6] = opa[i];
    #pragma unroll
    for (int c = 0; c < 3; c++) buf[7 + c]  = sca[3 * i + c];
    {
        float4 r4 = reinterpret_cast<const float4*>(rot)[i];
        buf[10] = r4.x; buf[11] = r4.y; buf[12] = r4.z; buf[13] = r4.w;
    }
    #pragma unroll
    for (int c = 0; c < 3; c++) buf[14 + c] = fdc[3 * i + c];
    buf[17] = kp[i];
    const float4* ip = reinterpret_cast<const float4*>(ins) + (size_t)i * 8;
    #pragma unroll
    for (int q = 0; q < 8; q++) {
        float4 v = ip[q];
        buf[18 + 4 * q + 0] = v.x; buf[18 + 4 * q + 1] = v.y;
        buf[18 + 4 * q + 2] = v.z; buf[18 + 4 * q + 3] = v.w;
    }
    const float4* mp = reinterpret_cast<const float4*>(mot) + (size_t)i * 4;
    #pragma unroll
    for (int q = 0; q < 4; q++) {
        float4 v = mp[q];
        buf[50 + 4 * q + 0] = v.x; buf[50 + 4 * q + 1] = v.y;
        buf[50 + 4 * q + 2] = v.z; buf[50 + 4 * q + 3] = v.w;
    }
}

// write buf (66 floats) to out row i, alignment-split for max vector width.
// row byte offset = i*264; even i -> 16B aligned, odd i -> 8B aligned.
__device__ __forceinline__ void store_row(int i, const float* buf, float* out) {
    float* o = out + (size_t)i * NCH;
    if ((i & 1) == 0) {
        float4* o4 = reinterpret_cast<float4*>(o);
        #pragma unroll
        for (int q = 0; q < 16; q++)
            o4[q] = make_float4(buf[4 * q], buf[4 * q + 1], buf[4 * q + 2], buf[4 * q + 3]);
        reinterpret_cast<float2*>(o)[32] = make_float2(buf[64], buf[65]);
    } else {
        reinterpret_cast<float2*>(o)[0] = make_float2(buf[0], buf[1]);
        float4* o4 = reinterpret_cast<float4*>(o + 2);
        #pragma unroll
        for (int q = 0; q < 16; q++)
            o4[q] = make_float4(buf[4 * q + 2], buf[4 * q + 3], buf[4 * q + 4], buf[4 * q + 5]);
    }
}

// ---------------- kernels ----------------
// count + phase-1 softmax sums into per-replica accumulators
__global__ void k1(const float* __restrict__ cen, const float* __restrict__ kp,
                   const int* __restrict__ gid) {
    int i = blockIdx.x * blockDim.x + threadIdx.x;
    if (i >= BN) return;
    int g = gid[i];
    if (g < 0) return;
    int s = seg_of(i, g) + (blockIdx.x & (REPL - 1)) * NSEG;
    atomicAdd(&g_s.cnt[s], 1);
    float e = __expf(kp[i]);
    red_add_v4(&g_s.p1[s].x, e, e * cen[3 * i + 0], e * cen[3 * i + 1], e * cen[3 * i + 2]);
}

// collapse phase-1 replicas into replica 0
__global__ void k_p1red() {
    int s = blockIdx.x * blockDim.x + threadIdx.x;
    if (s >= NSEG) return;
    int cnt = 0;
    float4 acc = make_float4(0.f, 0.f, 0.f, 0.f);
    #pragma unroll
    for (int r = 0; r < REPL; r++) {
        cnt += g_s.cnt[r * NSEG + s];
        float4 p = g_s.p1[r * NSEG + s];
        acc.x += p.x; acc.y += p.y; acc.z += p.z; acc.w += p.w;
    }
    g_s.cnt[s] = cnt;
    g_s.p1[s]  = acc;
}

// activity + weighted accumulation (active) OR direct row passthrough
// (inactive/invalid) written under the atomic shadow
__global__ void __launch_bounds__(256)
k2(const float* __restrict__ cen, const float* __restrict__ off,
   const float* __restrict__ opa, const float* __restrict__ sca,
   const float* __restrict__ rot, const float* __restrict__ fdc,
   const float* __restrict__ kp,  const float* __restrict__ ins,
   const float* __restrict__ mot, const int* __restrict__ gid,
   float* __restrict__ out) {
    int i = blockIdx.x * blockDim.x + threadIdx.x;
    if (i >= BN) return;
    int g = gid[i];
    int s = 0;
    unsigned char f = 0;
    float k0 = 0.0f;
    if (g >= 0) {
        s = seg_of(i, g);
        if (g_s.cnt[s] >= 2) {
            float4 p = g_s.p1[s];
            float zinv = 1.0f / fmaxf(p.x, 1e-20f);
            float dx = cen[3 * i + 0] - p.y * zinv;
            float dy = cen[3 * i + 1] - p.z * zinv;
            float dz = cen[3 * i + 2] - p.w * zinv;
            if (sqrtf(dx * dx + dy * dy + dz * dz) <= THR) {
                f = 1;
                k0 = kp[i];
            }
        }
    }
    g_flags[i] = f;

    float buf[NCH];
    load_row(i, buf, cen, off, opa, sca, rot, fdc, kp, ins, mot);

    if (f) {
        float e = __expf(k0);
        int sr = s + (blockIdx.x & (REPL - 1)) * NSEG;
        float* ws = &g_s.wsum[(size_t)sr * WCH];
        #pragma unroll
        for (int q = 0; q < 16; q++)
            red_add_v4(ws + 4 * q,
                       e * buf[4 * q + 0], e * buf[4 * q + 1],
                       e * buf[4 * q + 2], e * buf[4 * q + 3]);
        red_add_v4(ws + 64, e * buf[64], e * buf[65], e, 0.0f);
        unsigned long long key =
            ((unsigned long long)(~fok(k0)) << 32) | (unsigned)i;
        atomicMin(&g_repkey[sr], key);
    } else {
        // inactive or invalid: final value is the raw row -> write it now,
        // overlapped with the LTS-atomic-bound work of other warps
        store_row(i, buf, out);
    }
}

// warp-per-segment finalize: collapse replicas, means, rotation norm, mkeep, rep
__global__ void __launch_bounds__(256)
k_seg() {
    const unsigned FULL = 0xFFFFFFFFu;
    int warp = (blockIdx.x * blockDim.x + threadIdx.x) >> 5;
    int lane = threadIdx.x & 31;
    if (warp >= NSEG) return;
    int s = warp;

    // lane c owns channels c, c+32, c+64 (coalesced across the warp)
    float a0 = 0.f, a1 = 0.f, a2 = 0.f;
    #pragma unroll
    for (int r = 0; r < REPL; r++) {
        const float* ws = &g_s.wsum[(size_t)(r * NSEG + s) * WCH];
        a0 += ws[lane];
        a1 += ws[lane + 32];
        if (lane < 4) a2 += ws[lane + 64];
    }
    // z2 lives at channel 66 -> lane 2 of the third group
    float z2   = __shfl_sync(FULL, a2, 2);
    float zinv = 1.0f / fmaxf(z2, 1e-20f);
    a0 *= zinv; a1 *= zinv; a2 *= zinv;

    // rotation channels 10..13 (group 0)
    float r10 = __shfl_sync(FULL, a0, 10);
    float r11 = __shfl_sync(FULL, a0, 11);
    float r12 = __shfl_sync(FULL, a0, 12);
    float r13 = __shfl_sync(FULL, a0, 13);
    float nr  = sqrtf(r10 * r10 + r11 * r11 + r12 * r12 + r13 * r13);
    float ri  = 1.0f / fmaxf(nr, 1e-12f);
    if (lane >= 10 && lane <= 13) a0 *= ri;

    // representative key: min over replicas (lane 0), broadcast
    unsigned long long key = 0xFFFFFFFFFFFFFFFFull;
    if (lane == 0) {
        #pragma unroll
        for (int r = 0; r < REPL; r++) {
            unsigned long long k = g_repkey[r * NSEG + s];
            if (k < key) key = k;
        }
        g_rep[s] = (int)(unsigned)(key & 0xFFFFFFFFull);
    }
    key = __shfl_sync(FULL, key, 0);
    float m2 = kof(~(unsigned)(key >> 32));
    if (lane == 17) a0 = m2;   // mkeep = segment max keep over active

    float* r = &g_srow[(size_t)s * WCH];
    r[lane]      = a0;
    r[lane + 32] = a1;
    if (lane < 2) r[lane + 64] = a2;   // channels 64, 65
}

// active rows only: gather finalized segment row (L2-resident), apply sfac,
// write the row. Inactive rows were already written by k2.
__global__ void __launch_bounds__(256)
k3(const int* __restrict__ gid, float* __restrict__ out) {
    int i = blockIdx.x * blockDim.x + threadIdx.x;
    if (i >= BN) return;
    if (!g_flags[i]) return;
    int s = seg_of(i, gid[i]);

    float buf[NCH];
    const float4* r4 = reinterpret_cast<const float4*>(&g_srow[(size_t)s * WCH]);
    #pragma unroll
    for (int q = 0; q < 16; q++) {
        float4 v = __ldg(r4 + q);
        buf[4 * q + 0] = v.x; buf[4 * q + 1] = v.y;
        buf[4 * q + 2] = v.z; buf[4 * q + 3] = v.w;
    }
    {
        float4 v = __ldg(r4 + 16);   // channels 64,65 (+ z2, pad)
        buf[64] = v.x; buf[65] = v.y;
    }
    float sfac = (i == g_rep[s]) ? 1.0f : DKS;
    buf[6]  *= sfac;
    buf[17] *= sfac;

    store_row(i, buf, out);
}

// ---------------- launcher ----------------
extern "C" void kernel_launch(void* const* d_in, const int* in_sizes, int n_in,
                              void* d_out, int out_size) {
    const float* cen = (const float*)d_in[0];
    const float* off = (const float*)d_in[1];
    const float* opa = (const float*)d_in[2];
    const float* sca = (const float*)d_in[3];
    const float* rot = (const float*)d_in[4];
    const float* fdc = (const float*)d_in[5];
    const float* kp  = (const float*)d_in[6];
    const float* ins = (const float*)d_in[7];
    const float* mot = (const float*)d_in[8];
    const int*   gid = (const int*)d_in[9];
    float* out = (float*)d_out;

    // two memset nodes total: one big zero, one 0xFF for the min-keys
    void *p_s, *p_key;
    cudaGetSymbolAddress(&p_s,   g_s);
    cudaGetSymbolAddress(&p_key, g_repkey);
    cudaMemsetAsync(p_s,   0,    sizeof(Scratch));
    cudaMemsetAsync(p_key, 0xFF, (size_t)REPL * NSEG * sizeof(unsigned long long));

    const int TB = 256;
    const int GB = (BN + TB - 1) / TB;   // 2880

    k1     <<<GB, TB>>>(cen, kp, gid);
    k_p1red<<<NSEG / TB, TB>>>();
    k2     <<<GB, TB>>>(cen, off, opa, sca, rot, fdc, kp, ins, mot, gid, out);
    k_seg  <<<(NSEG * 32) / TB, TB>>>();
    k3     <<<GB, TB>>>(gid, out);
}

// round 11
// speedup vs baseline: 1.0849x; 1.0849x over previous
#include <cuda_runtime.h>
#include <math.h>

#define BN    737280      // total elements (8 * 92160)
#define BNH   368640      // BN / 2 (k1 ILP split)
#define NPIX  92160       // elements per (b,t) slice
#define NTRK  512
#define NSEG  4096        // 8 * 512
#define NCH   66
#define WCH   68          // padded accumulator row (16B-aligned stride)
#define REPL  4           // accumulator replicas (contention spreading)
#define THR   2.0f
#define DKS   0.05f

// ---------------- scratch (device globals; no allocation) ----------------
// single struct so one memset clears everything that needs zeroing
struct Scratch {
    int    cnt[REPL * NSEG];
    float4 p1[REPL * NSEG];              // {z1, wx, wy, wz}
    float  wsum[REPL * NSEG * WCH];      // [0..65]=w*ch, [66]=z2
};
__device__ __align__(16) Scratch        g_s;
__device__ unsigned long long           g_repkey[REPL * NSEG];  // (~fok(k0))<<32 | idx
__device__ __align__(16) float          g_srow[NSEG * WCH];     // finalized segment row
__device__ int                          g_rep[NSEG];
__device__ unsigned char                g_flags[BN];

// ordered-uint mapping for floats (bijective, order-preserving)
__device__ __forceinline__ unsigned fok(float f) {
    unsigned b = __float_as_uint(f);
    return (b & 0x80000000u) ? ~b : (b | 0x80000000u);
}
__device__ __forceinline__ float kof(unsigned u) {
    unsigned b = (u & 0x80000000u) ? (u & 0x7FFFFFFFu) : ~u;
    return __uint_as_float(b);
}
__device__ __forceinline__ int seg_of(int i, int g) {
    return (i / NPIX) * NTRK + g;
}
__device__ __forceinline__ void red_add_v4(float* p, float a, float b, float c, float d) {
    asm volatile("red.global.add.v4.f32 [%0], {%1, %2, %3, %4};"
                 :: "l"(p), "f"(a), "f"(b), "f"(c), "f"(d) : "memory");
}

// load all 66 channels for element i into buf
// order: center(0-2) offset(3-5) opacity(6) scale(7-9) rotation(10-13)
//        feat_dc(14-16) keep(17) inst(18-49) motion(50-65)
__device__ __forceinline__ void load_row(
    int i, float* buf,
    const float* __restrict__ cen, const float* __restrict__ off,
    const float* __restrict__ opa, const float* __restrict__ sca,
    const float* __restrict__ rot, const float* __restrict__ fdc,
    const float* __restrict__ kp,  const float* __restrict__ ins,
    const float* __restrict__ mot) {
    #pragma unroll
    for (int c = 0; c < 3; c++) buf[c]      = cen[3 * i + c];
    #pragma unroll
    for (int c = 0; c < 3; c++) buf[3 + c]  = off[3 * i + c];
    buf[6] = opa[i];
    #pragma unroll
    for (int c = 0; c < 3; c++) buf[7 + c]  = sca[3 * i + c];
    {
        float4 r4 = reinterpret_cast<const float4*>(rot)[i];
        buf[10] = r4.x; buf[11] = r4.y; buf[12] = r4.z; buf[13] = r4.w;
    }
    #pragma unroll
    for (int c = 0; c < 3; c++) buf[14 + c] = fdc[3 * i + c];
    buf[17] = kp[i];
    const float4* ip = reinterpret_cast<const float4*>(ins) + (size_t)i * 8;
    #pragma unroll
    for (int q = 0; q < 8; q++) {
        float4 v = ip[q];
        buf[18 + 4 * q + 0] = v.x; buf[18 + 4 * q + 1] = v.y;
        buf[18 + 4 * q + 2] = v.z; buf[18 + 4 * q + 3] = v.w;
    }
    const float4* mp = reinterpret_cast<const float4*>(mot) + (size_t)i * 4;
    #pragma unroll
    for (int q = 0; q < 4; q++) {
        float4 v = mp[q];
        buf[50 + 4 * q + 0] = v.x; buf[50 + 4 * q + 1] = v.y;
        buf[50 + 4 * q + 2] = v.z; buf[50 + 4 * q + 3] = v.w;
    }
}

// ---------------- kernels ----------------
// count + phase-1 softmax sums into per-replica accumulators (2 elems/thread)
__global__ void __launch_bounds__(256)
k1(const float* __restrict__ cen, const float* __restrict__ kp,
   const int* __restrict__ gid) {
    int t = blockIdx.x * blockDim.x + threadIdx.x;
    int rbase = (blockIdx.x & (REPL - 1)) * NSEG;
    #pragma unroll
    for (int h = 0; h < 2; h++) {
        int i = t + h * BNH;
        int g = gid[i];
        if (g >= 0) {
            int s = seg_of(i, g) + rbase;
            atomicAdd(&g_s.cnt[s], 1);
            float e = __expf(kp[i]);
            red_add_v4(&g_s.p1[s].x, e,
                       e * cen[3 * i + 0], e * cen[3 * i + 1], e * cen[3 * i + 2]);
        }
    }
}

// activity + weighted accumulation (per-replica) + representative key.
// Phase-1 replicas are summed inline (L1/L2-resident table).
__global__ void __launch_bounds__(256)
k2(const float* __restrict__ cen, const float* __restrict__ off,
   const float* __restrict__ opa, const float* __restrict__ sca,
   const float* __restrict__ rot, const float* __restrict__ fdc,
   const float* __restrict__ kp,  const float* __restrict__ ins,
   const float* __restrict__ mot, const int* __restrict__ gid) {
    int i = blockIdx.x * blockDim.x + threadIdx.x;
    if (i >= BN) return;
    int g = gid[i];
    int s = 0;
    unsigned char f = 0;
    float k0 = 0.0f;
    if (g >= 0) {
        s = seg_of(i, g);
        int cnt = 0;
        float z1 = 0.f, wx = 0.f, wy = 0.f, wz = 0.f;
        #pragma unroll
        for (int r = 0; r < REPL; r++) {
            cnt += __ldg(&g_s.cnt[r * NSEG + s]);
            float4 p = __ldg(&g_s.p1[r * NSEG + s]);
            z1 += p.x; wx += p.y; wy += p.z; wz += p.w;
        }
        if (cnt >= 2) {
            float zinv = 1.0f / fmaxf(z1, 1e-20f);
            float dx = cen[3 * i + 0] - wx * zinv;
            float dy = cen[3 * i + 1] - wy * zinv;
            float dz = cen[3 * i + 2] - wz * zinv;
            if (sqrtf(dx * dx + dy * dy + dz * dz) <= THR) {
                f = 1;
                k0 = kp[i];
            }
        }
    }
    g_flags[i] = f;
    if (!f) return;

    float buf[NCH];
    load_row(i, buf, cen, off, opa, sca, rot, fdc, kp, ins, mot);
    float e = __expf(k0);
    int sr = s + (blockIdx.x & (REPL - 1)) * NSEG;
    float* ws = &g_s.wsum[(size_t)sr * WCH];
    #pragma unroll
    for (int q = 0; q < 16; q++)
        red_add_v4(ws + 4 * q,
                   e * buf[4 * q + 0], e * buf[4 * q + 1],
                   e * buf[4 * q + 2], e * buf[4 * q + 3]);
    red_add_v4(ws + 64, e * buf[64], e * buf[65], e, 0.0f);

    unsigned long long key =
        ((unsigned long long)(~fok(k0)) << 32) | (unsigned)i;
    atomicMin(&g_repkey[sr], key);
}

// warp-per-segment finalize: collapse replicas, means, rotation norm, mkeep, rep
__global__ void __launch_bounds__(256)
k_seg() {
    const unsigned FULL = 0xFFFFFFFFu;
    int warp = (blockIdx.x * blockDim.x + threadIdx.x) >> 5;
    int lane = threadIdx.x & 31;
    if (warp >= NSEG) return;
    int s = warp;

    // lane c owns channels c, c+32, c+64 (coalesced across the warp)
    float a0 = 0.f, a1 = 0.f, a2 = 0.f;
    #pragma unroll
    for (int r = 0; r < REPL; r++) {
        const float* ws = &g_s.wsum[(size_t)(r * NSEG + s) * WCH];
        a0 += ws[lane];
        a1 += ws[lane + 32];
        if (lane < 4) a2 += ws[lane + 64];
    }
    // z2 lives at channel 66 -> lane 2 of the third group
    float z2   = __shfl_sync(FULL, a2, 2);
    float zinv = 1.0f / fmaxf(z2, 1e-20f);
    a0 *= zinv; a1 *= zinv; a2 *= zinv;

    // rotation channels 10..13 (group 0)
    float r10 = __shfl_sync(FULL, a0, 10);
    float r11 = __shfl_sync(FULL, a0, 11);
    float r12 = __shfl_sync(FULL, a0, 12);
    float r13 = __shfl_sync(FULL, a0, 13);
    float nr  = sqrtf(r10 * r10 + r11 * r11 + r12 * r12 + r13 * r13);
    float ri  = 1.0f / fmaxf(nr, 1e-12f);
    if (lane >= 10 && lane <= 13) a0 *= ri;

    // representative key: min over replicas (lane 0), broadcast
    unsigned long long key = 0xFFFFFFFFFFFFFFFFull;
    if (lane == 0) {
        #pragma unroll
        for (int r = 0; r < REPL; r++) {
            unsigned long long k = g_repkey[r * NSEG + s];
            if (k < key) key = k;
        }
        g_rep[s] = (int)(unsigned)(key & 0xFFFFFFFFull);
    }
    key = __shfl_sync(FULL, key, 0);
    float m2 = kof(~(unsigned)(key >> 32));
    if (lane == 17) a0 = m2;   // mkeep = segment max keep over active

    float* r = &g_srow[(size_t)s * WCH];
    r[lane]      = a0;
    r[lane + 32] = a1;
    if (lane < 2) r[lane + 64] = a2;   // channels 64, 65
}

// output: gather (segment row for active, raw channels for inactive),
// stage in smem, write fully coalesced
__global__ void __launch_bounds__(128)
k3(const float* __restrict__ cen, const float* __restrict__ off,
   const float* __restrict__ opa, const float* __restrict__ sca,
   const float* __restrict__ rot, const float* __restrict__ fdc,
   const float* __restrict__ kp,  const float* __restrict__ ins,
   const float* __restrict__ mot, const int* __restrict__ gid,
   float* __restrict__ out) {
    __shared__ float stage[128 * NCH];   // 33,792 B
    int tid = threadIdx.x;
    int i = blockIdx.x * 128 + tid;

    float buf[NCH];
    if (g_flags[i]) {
        int s = seg_of(i, gid[i]);
        const float4* r4 = reinterpret_cast<const float4*>(&g_srow[(size_t)s * WCH]);
        #pragma unroll
        for (int q = 0; q < 16; q++) {
            float4 v = __ldg(r4 + q);
            buf[4 * q + 0] = v.x; buf[4 * q + 1] = v.y;
            buf[4 * q + 2] = v.z; buf[4 * q + 3] = v.w;
        }
        {
            float4 v = __ldg(r4 + 16);   // channels 64,65 (+ z2, pad)
            buf[64] = v.x; buf[65] = v.y;
        }
        float sfac = (i == g_rep[s]) ? 1.0f : DKS;
        buf[6]  *= sfac;
        buf[17] *= sfac;
    } else {
        load_row(i, buf, cen, off, opa, sca, rot, fdc, kp, ins, mot);
    }
    #pragma unroll
    for (int c = 0; c < NCH; c++) stage[tid * NCH + c] = buf[c];
    __syncthreads();

    float4* dst = reinterpret_cast<float4*>(out + (size_t)blockIdx.x * 128 * NCH);
    const float4* src = reinterpret_cast<const float4*>(stage);
    for (int idx = tid; idx < (128 * NCH) / 4; idx += 128)
        dst[idx] = src[idx];
}

// ---------------- launcher ----------------
extern "C" void kernel_launch(void* const* d_in, const int* in_sizes, int n_in,
                              void* d_out, int out_size) {
    const float* cen = (const float*)d_in[0];
    const float* off = (const float*)d_in[1];
    const float* opa = (const float*)d_in[2];
    const float* sca = (const float*)d_in[3];
    const float* rot = (const float*)d_in[4];
    const float* fdc = (const float*)d_in[5];
    const float* kp  = (const float*)d_in[6];
    const float* ins = (const float*)d_in[7];
    const float* mot = (const float*)d_in[8];
    const int*   gid = (const int*)d_in[9];
    float* out = (float*)d_out;

    // two memset nodes total: one big zero, one 0xFF for the min-keys
    void *p_s, *p_key;
    cudaGetSymbolAddress(&p_s,   g_s);
    cudaGetSymbolAddress(&p_key, g_repkey);
    cudaMemsetAsync(p_s,   0,    sizeof(Scratch));
    cudaMemsetAsync(p_key, 0xFF, (size_t)REPL * NSEG * sizeof(unsigned long long));

    const int TB = 256;
    k1   <<<BNH / TB, TB>>>(cen, kp, gid);                               // 1440 blocks
    k2   <<<BN / TB, TB>>>(cen, off, opa, sca, rot, fdc, kp, ins, mot, gid);
    k_seg<<<(NSEG * 32) / TB, TB>>>();
    k3   <<<BN / 128, 128>>>(cen, off, opa, sca, rot, fdc, kp, ins, mot, gid, out);
}